// round 9
// baseline (speedup 1.0000x reference)
#include <cuda_runtime.h>
#include <cstdint>

// Problem constants (fixed by the dataset)
#define B_    4
#define N_    8192
#define M_    2048
#define K_    32
#define C_    64
#define NBINS 16

#define MPB     4     // m-rows per block (TWO warps per row in phase 2)
#define THREADS 256

#define G_STRIDE 36   // floats per (m,k) g-record: 32 data + 4 pad

typedef unsigned long long ull;

__device__ int g_idx_is64;

// Detect whether nn_index buffer is int64 or int32 (values < 8192 => high
// words of int64 all zero; int32 data makes odd words random). Deterministic.
__global__ void detect_idx_dtype_kernel(const int* __restrict__ words) {
    __shared__ int any_nonzero;
    if (threadIdx.x == 0) any_nonzero = 0;
    __syncthreads();
    int local = 0;
    for (int i = threadIdx.x; i < 2048; i += blockDim.x) {
        if (words[2 * i + 1] != 0) local = 1;
    }
    if (local) atomicOr(&any_nonzero, 1);
    __syncthreads();
    if (threadIdx.x == 0) g_idx_is64 = any_nonzero ? 0 : 1;
}

// Packed fp32x2 ops (Blackwell): one instruction, two fp32 lanes.
#define FMA2(d, a, b, c) \
    asm("fma.rn.f32x2 %0, %1, %2, %3;" : "=l"(d) : "l"(a), "l"(b), "l"(c))
#define ADD2(d, a, b) \
    asm("add.rn.f32x2 %0, %1, %2;" : "=l"(d) : "l"(a), "l"(b))

__global__ __launch_bounds__(THREADS, 6) void fuzzy_sphere_kernel(
    const float* __restrict__ database,      // (B, N, 3)
    const float* __restrict__ query,         // (B, M, 3)
    const void*  __restrict__ nn_index_raw,  // (B, M, K) int64 or int32
    const float* __restrict__ nn_dist,       // (B, M, K)
    const float* __restrict__ feats,         // (B, N, C)
    const float* __restrict__ fw,            // (NBINS, C, 1)
    float* __restrict__ out)                 // (B, M, C)
{
    __shared__ float sg[MPB * K_ * G_STRIDE];  // duplicated g-pairs, 18 KB
    __shared__ int   soff[MPB * K_];           // feature row offsets
    __shared__ ull   sred[MPB * 32];           // cross-warp partial sums, 1 KB

    const int tid  = threadIdx.x;
    const int lane = tid & 31;
    const int wid  = tid >> 5;                 // 0..7
    const int row  = wid >> 1;                 // m-row within block (0..3)
    const int side = wid & 1;                  // bin half: 0 -> bins 0-7, 1 -> 8-15
    const int t2   = lane * 2;                 // channel pair base
    const int gm0  = blockIdx.x * MPB;

    // -------- This warp's HALF of the weight table in registers (8 bins) -----
    ull wreg[8];
    #pragma unroll
    for (int j = 0; j < 8; j++)
        wreg[j] = *(const ull*)(fw + (8 * side + j) * C_ + t2);

    const int is64 = g_idx_is64;

    // ---------------- Phase 1: factorized bin coefficients (128 tasks) ------
    if (tid < MPB * K_) {
        const int mi = tid >> 5;            // m-row within block
        const int k  = lane;                // neighbor index
        const int gm = gm0 + mi;            // flattened b*M + m
        const int b  = gm >> 11;            // gm / M_

        int nidx;
        if (is64) nidx = (int)((const long long*)nn_index_raw)[(size_t)gm * K_ + k];
        else      nidx = ((const int*)nn_index_raw)[(size_t)gm * K_ + k];

        const float d  = nn_dist[(size_t)gm * K_ + k];
        const float qx = query[gm * 3 + 0];
        const float qy = query[gm * 3 + 1];
        const float qz = query[gm * 3 + 2];
        const float* dbp = database + ((size_t)b * N_ + nidx) * 3;
        const float x = dbp[0] - qx;
        const float y = dbp[1] - qy;
        const float z = dbp[2] - qz;

        const float azimuth = atan2f(y, x) + 3.14159265358979323846f;
        float ct = z / (d + 1e-8f);
        ct = fminf(fmaxf(ct, -1.0f), 1.0f);
        const float elevation = acosf(ct);

        const float SC = 0.63661977236758134f;   // 4/(2pi) == 2/pi
        const float ab = azimuth   * SC;
        const float eb = elevation * SC;
        float rb = d / 0.05f;
        rb = fminf(fmaxf(rb, 0.0f), 2.0f - 1e-6f);

        const float afl = floorf(ab), efl = floorf(eb), rfl = floorf(rb);
        const float afr = ab - afl,   efr = eb - efl,   rfr = rb - rfl;
        const float ai = 1.0f - afr,  ei = 1.0f - efr,  ri = 1.0f - rfr;

        const int a0 = ((int)afl) & 3;
        const int ef = (int)efl;             // 0,1,(2 at poles)
        const int rf = (int)rfl;             // 0 or 1

        // Factorized axis coefficients (exact: ei+efr == 1, ri+rfr == 1)
        const float FE0 = (ef == 0) ? ei  : 0.0f;
        const float FE1 = (ef == 0) ? efr : 1.0f;
        const float FR0 = (rf == 0) ? ri  : 0.0f;
        const float FR1 = (rf == 0) ? rfr : 1.0f;

        const float t00 = FE0 * FR0, t01 = FE0 * FR1;
        const float t10 = FE1 * FR0, t11 = FE1 * FR1;

        // FA[A]: ai at a0, afr at (a0+1)&3, else 0 — no dynamic indexing
        const float fa0 = (a0 == 0) ? ai : ((a0 == 3) ? afr : 0.0f);
        const float fa1 = (a0 == 1) ? ai : ((a0 == 0) ? afr : 0.0f);
        const float fa2 = (a0 == 2) ? ai : ((a0 == 1) ? afr : 0.0f);
        const float fa3 = (a0 == 3) ? ai : ((a0 == 2) ? afr : 0.0f);

        float* dst = sg + (mi * K_ + k) * G_STRIDE;
        const float fa[4] = {fa0, fa1, fa2, fa3};
        #pragma unroll
        for (int A = 0; A < 4; A++) {
            const float g00 = fa[A] * t00, g01 = fa[A] * t01;
            const float g10 = fa[A] * t10, g11 = fa[A] * t11;
            ((float4*)dst)[2 * A + 0] = make_float4(g00, g00, g01, g01);
            ((float4*)dst)[2 * A + 1] = make_float4(g10, g10, g11, g11);
        }

        soff[mi * K_ + k] = (b * N_ + nidx) * C_;
    }
    __syncthreads();

    // ---------------- Phase 2: two warps per m-row (bin halves) --------------
    const int gm = gm0 + row;

    // This warp's half of each g-record: 16 floats at offset side*16
    const float* mygd  = sg + row * K_ * G_STRIDE + side * 16;
    const int*   myoff = soff + row * K_;

    ull acc = 0;                          // f32x2 (0,0)

    // 2-deep software pipeline for the gathered feature loads.
    ull nf0 = *(const ull*)(feats + myoff[0] + t2);
    ull nf1 = *(const ull*)(feats + myoff[1] + t2);

    #pragma unroll 4
    for (int k = 0; k < K_; k++) {
        const ull nf = (k & 1) ? nf1 : nf0;
        if (k + 2 < K_) {
            const ull nfp = *(const ull*)(feats + myoff[k + 2] + t2);
            if (k & 1) nf1 = nfp; else nf0 = nfp;
        }

        // 8 duplicated g-pairs for this (k, side): 4 broadcast LDS.128
        const ulonglong2* gp = (const ulonglong2*)(mygd + k * G_STRIDE);

        ull ws0 = 0, ws1 = 0, ws2 = 0, ws3 = 0;
        {
            const ulonglong2 ua = gp[0];
            const ulonglong2 ub = gp[1];
            FMA2(ws0, ua.x, wreg[0], ws0);
            FMA2(ws1, ua.y, wreg[1], ws1);
            FMA2(ws2, ub.x, wreg[2], ws2);
            FMA2(ws3, ub.y, wreg[3], ws3);
        }
        {
            const ulonglong2 ua = gp[2];
            const ulonglong2 ub = gp[3];
            FMA2(ws0, ua.x, wreg[4], ws0);
            FMA2(ws1, ua.y, wreg[5], ws1);
            FMA2(ws2, ub.x, wreg[6], ws2);
            FMA2(ws3, ub.y, wreg[7], ws3);
        }
        ull wsA, wsB, ws;
        ADD2(wsA, ws0, ws1);
        ADD2(wsB, ws2, ws3);
        ADD2(ws, wsA, wsB);
        FMA2(acc, nf, ws, acc);
    }

    // ---------------- Combine the two bin-half partials ----------------------
    if (side == 0) sred[row * 32 + lane] = acc;
    __syncthreads();
    if (side == 1) {
        ull other = sred[row * 32 + lane];
        ADD2(acc, acc, other);
        *(ull*)(out + (size_t)gm * C_ + t2) = acc;
    }
}

extern "C" void kernel_launch(void* const* d_in, const int* in_sizes, int n_in,
                              void* d_out, int out_size) {
    const float* database = (const float*)d_in[0];
    const float* query    = (const float*)d_in[1];
    const void*  nn_index = (const void*) d_in[2];
    // d_in[3] = nn_count (unused by the reference einsum)
    const float* nn_dist  = (const float*)d_in[4];
    const float* feats    = (const float*)d_in[5];
    const float* fw       = (const float*)d_in[6];
    float* out = (float*)d_out;

    detect_idx_dtype_kernel<<<1, 256>>>((const int*)nn_index);

    const int blocks = (B_ * M_) / MPB;   // 2048
    fuzzy_sphere_kernel<<<blocks, THREADS>>>(
        database, query, nn_index, nn_dist, feats, fw, out);
}